// round 5
// baseline (speedup 1.0000x reference)
#include <cuda_runtime.h>
#include <math.h>

#define NTOK 8192
#define DM   512
#define NE   8
#define TOPK 2
#define NASSIGN (NTOK * TOPK)

// ---------------- scratch (device globals: no allocation allowed) ----------------
__device__ int   g_count[NE];          // tokens per expert
__device__ int   g_offs[NE];           // exclusive prefix of counts
__device__ int   g_cursor[NE];         // assignment cursors
__device__ int   g_eidx[NTOK][TOPK];   // chosen expert ids per token
__device__ float g_gate[NTOK][TOPK];   // softmaxed gate values per token
__device__ int   g_tok[NASSIGN];       // gathered token index per slot
__device__ int   g_slot[NTOK][TOPK];   // slot (row in g_y) per (token, k)
__device__ float g_y[(size_t)NASSIGN * DM];  // 32 MB expert-output scratch

// ---------------- 0: reset counters ----------------
__global__ void init_kernel() {
    int t = threadIdx.x;
    if (t < NE) g_count[t] = 0;
}

// ---------------- 1: gating (warp per token) ----------------
__global__ void gate_kernel(const float* __restrict__ x,
                            const float* __restrict__ wg) {
    __shared__ float sw[DM * NE];                 // 16 KB: w_gate [d][e]
    int tid = threadIdx.x;                        // 256 threads
    for (int i = tid; i < DM * NE; i += 256) sw[i] = wg[i];
    __syncthreads();

    int warp  = tid >> 5;
    int lane  = tid & 31;
    int token = blockIdx.x * 8 + warp;            // grid = 1024 blocks -> 8192 tokens

    const float* xr = x + (size_t)token * DM;
    float acc[NE];
#pragma unroll
    for (int e = 0; e < NE; e++) acc[e] = 0.f;

    for (int d = lane; d < DM; d += 32) {
        float xv = xr[d];
        const float* w = &sw[d * NE];
#pragma unroll
        for (int e = 0; e < NE; e++) acc[e] += xv * w[e];
    }
#pragma unroll
    for (int e = 0; e < NE; e++) {
#pragma unroll
        for (int off = 16; off > 0; off >>= 1)
            acc[e] += __shfl_xor_sync(0xFFFFFFFFu, acc[e], off);
    }

    if (lane == 0) {
        // top-2 (first index wins ties, matching lax.top_k)
        int i0 = 0; float v0 = acc[0];
#pragma unroll
        for (int e = 1; e < NE; e++) if (acc[e] > v0) { v0 = acc[e]; i0 = e; }
        int i1 = -1; float v1 = -3.0e38f;
#pragma unroll
        for (int e = 0; e < NE; e++) if (e != i0 && acc[e] > v1) { v1 = acc[e]; i1 = e; }

        // softmax over the two kept logits (v0 >= v1)
        float e1 = expf(v1 - v0);
        float inv = 1.f / (1.f + e1);
        float g0 = inv, g1 = e1 * inv;

        g_eidx[token][0] = i0;  g_eidx[token][1] = i1;
        g_gate[token][0] = g0;  g_gate[token][1] = g1;
        atomicAdd(&g_count[i0], 1);
        atomicAdd(&g_count[i1], 1);
    }
}

// ---------------- 2: tiny exclusive scan ----------------
__global__ void scan_kernel() {
    if (threadIdx.x == 0) {
        int acc = 0;
        for (int e = 0; e < NE; e++) {
            g_offs[e]   = acc;
            g_cursor[e] = acc;
            acc += g_count[e];
        }
    }
}

// ---------------- 3: slot assignment ----------------
__global__ void assign_kernel() {
    int n = blockIdx.x * blockDim.x + threadIdx.x;
    if (n >= NTOK) return;
#pragma unroll
    for (int k = 0; k < TOPK; k++) {
        int e   = g_eidx[n][k];
        int pos = atomicAdd(&g_cursor[e], 1);
        g_tok[pos]   = n;
        g_slot[n][k] = pos;
    }
}

// ---------------- 4: grouped expert GEMM (gathered A), 128x128x16 fp32 ----------------
// Register double-buffered: prefetch tile k+1 into regs during compute of tile k.
// y[slot, f] = sum_d x[token, d] * W[e, d, f]
__global__ void __launch_bounds__(256, 2)
expert_gemm(const float* __restrict__ x, const float* __restrict__ ew) {
    const int e   = blockIdx.z;
    const int cnt = g_count[e];
    const int m0  = blockIdx.y * 128;
    if (m0 >= cnt) return;
    const int n0   = blockIdx.x * 128;
    const int base = g_offs[e];

    __shared__ float As[16][132];   // A^T: [k][row], padded
    __shared__ float Bs[16][132];   // [k][col], padded

    const int tid = threadIdx.x;    // 256
    const int tx  = tid & 15;       // col group
    const int ty  = tid >> 4;       // row group

    // A-load mapping: thread -> (row = tid/4 + {0,64}, k4 = (tid%4)*4)
    const int ar = tid >> 2;
    const int ak = (tid & 3) * 4;
    const float* aptr[2];
    {
#pragma unroll
        for (int i = 0; i < 2; i++) {
            int r = m0 + ar + i * 64;
            int rc = (r < cnt) ? r : (cnt - 1);       // clamp (rows >= cnt never stored)
            int t  = g_tok[base + rc];
            aptr[i] = x + (size_t)t * DM;
        }
    }
    // B-load mapping: thread -> (row = tid/32 + {0,8}, col4 = (tid%32)*4)
    const int br = tid >> 5;
    const int bc = (tid & 31) * 4;
    const float* W = ew + (size_t)e * DM * DM;

    float acc[8][8];
#pragma unroll
    for (int i = 0; i < 8; i++)
#pragma unroll
        for (int j = 0; j < 8; j++) acc[i][j] = 0.f;

    // ---- prologue: load tile 0 into smem ----
    {
#pragma unroll
        for (int i = 0; i < 2; i++) {
            float4 v = *(const float4*)(aptr[i] + ak);
            int r = ar + i * 64;
            As[ak + 0][r] = v.x;
            As[ak + 1][r] = v.y;
            As[ak + 2][r] = v.z;
            As[ak + 3][r] = v.w;
        }
#pragma unroll
        for (int i = 0; i < 2; i++) {
            float4 v = *(const float4*)(W + (size_t)(br + i * 8) * DM + n0 + bc);
            *(float4*)&Bs[br + i * 8][bc] = v;
        }
    }
    __syncthreads();

    for (int k0 = 0; k0 < DM; k0 += 16) {
        // ---- prefetch next tile into registers (overlaps with FFMA below) ----
        float4 an[2], bn[2];
        const bool has_next = (k0 + 16) < DM;
        if (has_next) {
#pragma unroll
            for (int i = 0; i < 2; i++)
                an[i] = *(const float4*)(aptr[i] + k0 + 16 + ak);
#pragma unroll
            for (int i = 0; i < 2; i++)
                bn[i] = *(const float4*)(W + (size_t)(k0 + 16 + br + i * 8) * DM + n0 + bc);
        }

        // ---- compute current tile from smem ----
#pragma unroll
        for (int k = 0; k < 16; k++) {
            float4 a0 = *(float4*)&As[k][ty * 8];
            float4 a1 = *(float4*)&As[k][ty * 8 + 4];
            float4 b0 = *(float4*)&Bs[k][tx * 8];
            float4 b1 = *(float4*)&Bs[k][tx * 8 + 4];
            float a[8] = {a0.x, a0.y, a0.z, a0.w, a1.x, a1.y, a1.z, a1.w};
            float b[8] = {b0.x, b0.y, b0.z, b0.w, b1.x, b1.y, b1.z, b1.w};
#pragma unroll
            for (int i = 0; i < 8; i++)
#pragma unroll
                for (int j = 0; j < 8; j++) acc[i][j] += a[i] * b[j];
        }
        __syncthreads();

        // ---- commit prefetched regs to smem ----
        if (has_next) {
#pragma unroll
            for (int i = 0; i < 2; i++) {
                int r = ar + i * 64;
                As[ak + 0][r] = an[i].x;
                As[ak + 1][r] = an[i].y;
                As[ak + 2][r] = an[i].z;
                As[ak + 3][r] = an[i].w;
            }
#pragma unroll
            for (int i = 0; i < 2; i++)
                *(float4*)&Bs[br + i * 8][bc] = bn[i];
            __syncthreads();
        }
    }

#pragma unroll
    for (int i = 0; i < 8; i++) {
        int r = m0 + ty * 8 + i;
        if (r < cnt) {
            float* yrow = g_y + (size_t)(base + r) * DM + n0 + tx * 8;
            *(float4*)(yrow)     = make_float4(acc[i][0], acc[i][1], acc[i][2], acc[i][3]);
            *(float4*)(yrow + 4) = make_float4(acc[i][4], acc[i][5], acc[i][6], acc[i][7]);
        }
    }
}

// ---------------- 5: log-domain combine ----------------
__global__ void combine_kernel(float* __restrict__ out) {
    int n = blockIdx.x;
    int s0 = g_slot[n][0], s1 = g_slot[n][1];
    float g0 = g_gate[n][0], g1 = g_gate[n][1];
    const float* y0 = g_y + (size_t)s0 * DM;
    const float* y1 = g_y + (size_t)s1 * DM;
    float* o = out + (size_t)n * DM;
    for (int f = threadIdx.x; f < DM; f += 128) {
        float c = g0 * expf(y0[f]) + g1 * expf(y1[f]);
        // reference: zeros -> eps before log (can't hit here, but cheap to match)
        if (c == 0.f) c = 2.220446049250313e-16f;
        o[f] = logf(c);
    }
}

// ---------------- 6: balance loss (deterministic reduction) ----------------
__global__ void loss_kernel(float* __restrict__ out, int out_size) {
    __shared__ float s[NE][256];
    int tid = threadIdx.x;
    float imp[NE];
#pragma unroll
    for (int e = 0; e < NE; e++) imp[e] = 0.f;
    for (int n = tid; n < NTOK; n += 256) {
#pragma unroll
        for (int k = 0; k < TOPK; k++)
            imp[g_eidx[n][k]] += g_gate[n][k];
    }
#pragma unroll
    for (int e = 0; e < NE; e++) s[e][tid] = imp[e];
    __syncthreads();
    for (int st = 128; st > 0; st >>= 1) {
        if (tid < st) {
#pragma unroll
            for (int e = 0; e < NE; e++) s[e][tid] += s[e][tid + st];
        }
        __syncthreads();
    }
    if (tid == 0) {
        float mi = 0.f, ml = 0.f;
        float iv[NE], lv[NE];
        for (int e = 0; e < NE; e++) {
            iv[e] = s[e][0];
            lv[e] = (float)g_count[e];
            mi += iv[e]; ml += lv[e];
        }
        mi *= (1.f / NE); ml *= (1.f / NE);
        float vi = 0.f, vl = 0.f;
        for (int e = 0; e < NE; e++) {
            float di = iv[e] - mi, dl = lv[e] - ml;
            vi += di * di; vl += dl * dl;
        }
        vi *= (1.f / NE); vl *= (1.f / NE);
        float loss = vi / (mi * mi + 1e-10f) + vl / (ml * ml + 1e-10f);
        if (out_size > NTOK * DM) out[NTOK * DM] = loss;
    }
}

// ---------------- launch ----------------
extern "C" void kernel_launch(void* const* d_in, const int* in_sizes, int n_in,
                              void* d_out, int out_size) {
    const float* x  = (const float*)d_in[0];   // [8192, 512]
    const float* wg = (const float*)d_in[1];   // [512, 8]
    const float* ew = (const float*)d_in[2];   // [8, 512, 512]
    float* out = (float*)d_out;                // [8192*512] ++ [1] balance_loss

    init_kernel<<<1, 32>>>();
    gate_kernel<<<NTOK / 8, 256>>>(x, wg);
    scan_kernel<<<1, 32>>>();
    assign_kernel<<<NTOK / 256, 256>>>();
    {
        dim3 grid(DM / 128, NTOK / 128, NE);   // n-tiles, m-tiles (worst case), experts
        expert_gemm<<<grid, 256>>>(x, ew);
    }
    combine_kernel<<<NTOK, 128>>>(out);
    loss_kernel<<<1, 256>>>(out, out_size);
}

// round 6
// speedup vs baseline: 2.0628x; 2.0628x over previous
#include <cuda_runtime.h>
#include <math.h>

#define NTOK 8192
#define DM   512
#define NE   8
#define TOPK 2
#define NASSIGN (NTOK * TOPK)

// ---------------- scratch (device globals: no allocation allowed) ----------------
__device__ int   g_count[NE];          // tokens per expert
__device__ int   g_offs[NE];           // exclusive prefix of counts
__device__ int   g_cursor[NE];         // assignment cursors
__device__ int   g_eidx[NTOK][TOPK];   // chosen expert ids per token
__device__ float g_gate[NTOK][TOPK];   // softmaxed gate values per token
__device__ int   g_tok[NASSIGN];       // gathered token index per slot
__device__ int   g_slot[NTOK][TOPK];   // slot (row in g_y) per (token, k)
__device__ float g_y[(size_t)NASSIGN * DM];  // 32 MB expert-output scratch

__device__ __forceinline__ unsigned f2tf32(float f) {
    unsigned u;
    asm("cvt.rna.tf32.f32 %0, %1;" : "=r"(u) : "f"(f));
    return u;
}

__device__ __forceinline__ void mma_tf32(float d[4], const unsigned a[4], const unsigned b[2]) {
    asm volatile(
        "mma.sync.aligned.m16n8k8.row.col.f32.tf32.tf32.f32 "
        "{%0,%1,%2,%3}, {%4,%5,%6,%7}, {%8,%9}, {%0,%1,%2,%3};"
        : "+f"(d[0]), "+f"(d[1]), "+f"(d[2]), "+f"(d[3])
        : "r"(a[0]), "r"(a[1]), "r"(a[2]), "r"(a[3]), "r"(b[0]), "r"(b[1]));
}

// ---------------- 0: reset counters ----------------
__global__ void init_kernel() {
    int t = threadIdx.x;
    if (t < NE) g_count[t] = 0;
}

// ---------------- 1: gating (warp per token) ----------------
__global__ void gate_kernel(const float* __restrict__ x,
                            const float* __restrict__ wg) {
    __shared__ float sw[DM * NE];                 // 16 KB: w_gate [d][e]
    int tid = threadIdx.x;                        // 256 threads
    for (int i = tid; i < DM * NE; i += 256) sw[i] = wg[i];
    __syncthreads();

    int warp  = tid >> 5;
    int lane  = tid & 31;
    int token = blockIdx.x * 8 + warp;            // grid = 1024 blocks -> 8192 tokens

    const float* xr = x + (size_t)token * DM;
    float acc[NE];
#pragma unroll
    for (int e = 0; e < NE; e++) acc[e] = 0.f;

    for (int d = lane; d < DM; d += 32) {
        float xv = xr[d];
        const float* w = &sw[d * NE];
#pragma unroll
        for (int e = 0; e < NE; e++) acc[e] += xv * w[e];
    }
#pragma unroll
    for (int e = 0; e < NE; e++) {
#pragma unroll
        for (int off = 16; off > 0; off >>= 1)
            acc[e] += __shfl_xor_sync(0xFFFFFFFFu, acc[e], off);
    }

    if (lane == 0) {
        int i0 = 0; float v0 = acc[0];
#pragma unroll
        for (int e = 1; e < NE; e++) if (acc[e] > v0) { v0 = acc[e]; i0 = e; }
        int i1 = -1; float v1 = -3.0e38f;
#pragma unroll
        for (int e = 0; e < NE; e++) if (e != i0 && acc[e] > v1) { v1 = acc[e]; i1 = e; }

        float e1 = expf(v1 - v0);
        float inv = 1.f / (1.f + e1);
        float g0 = inv, g1 = e1 * inv;

        g_eidx[token][0] = i0;  g_eidx[token][1] = i1;
        g_gate[token][0] = g0;  g_gate[token][1] = g1;
        atomicAdd(&g_count[i0], 1);
        atomicAdd(&g_count[i1], 1);
    }
}

// ---------------- 2: tiny exclusive scan ----------------
__global__ void scan_kernel() {
    if (threadIdx.x == 0) {
        int acc = 0;
        for (int e = 0; e < NE; e++) {
            g_offs[e]   = acc;
            g_cursor[e] = acc;
            acc += g_count[e];
        }
    }
}

// ---------------- 3: slot assignment (block-aggregated atomics) ----------------
__global__ void assign_kernel() {
    __shared__ int loc[NE];     // per-block local counts
    __shared__ int bbase[NE];   // per-block global bases
    int tid = threadIdx.x;
    if (tid < NE) loc[tid] = 0;
    __syncthreads();

    int n = blockIdx.x * 256 + tid;
    int e[TOPK], p[TOPK];
#pragma unroll
    for (int k = 0; k < TOPK; k++) {
        e[k] = g_eidx[n][k];
        p[k] = atomicAdd(&loc[e[k]], 1);     // fast smem atomic
    }
    __syncthreads();
    if (tid < NE) bbase[tid] = atomicAdd(&g_cursor[tid], loc[tid]);
    __syncthreads();
#pragma unroll
    for (int k = 0; k < TOPK; k++) {
        int pos = bbase[e[k]] + p[k];
        g_tok[pos]   = n;
        g_slot[n][k] = pos;
    }
}

// ---------------- 4: grouped expert GEMM, TF32 mma.sync m16n8k8 ----------------
// CTA tile 128x128, k-tile 32, 8 warps in 2x4 (warp tile 64x32).
// y[slot, f] = sum_d x[token, d] * W[e, d, f]
#define AS_LD 36    // As[m][k] stride  -> A-frag LDS conflict-free
#define BS_LD 136   // Bs[k][n] stride  -> B-frag LDS conflict-free

__global__ void __launch_bounds__(256, 2)
expert_gemm(const float* __restrict__ x, const float* __restrict__ ew) {
    const int e   = blockIdx.z;
    const int cnt = g_count[e];
    const int m0  = blockIdx.y * 128;
    if (m0 >= cnt) return;
    const int n0   = blockIdx.x * 128;
    const int base = g_offs[e];

    __shared__ unsigned As[128][AS_LD];   // tf32 bits, [m][k]
    __shared__ unsigned Bs[32][BS_LD];    // tf32 bits, [k][n]

    const int tid  = threadIdx.x;   // 256
    const int lane = tid & 31;
    const int wid  = tid >> 5;
    const int wm   = (wid & 1) * 64;      // warp row origin
    const int wn   = (wid >> 1) * 32;     // warp col origin
    const int gr   = lane >> 2;           // group row   (0..7)
    const int gc   = lane & 3;            // group col   (0..3)

    // A global-load mapping: rows ar + {0,64}; k = 8*(tid&3) + {0,4}
    const int ar = tid >> 2;
    const int akb = (tid & 3) * 8;
    const float* aptr[2];
#pragma unroll
    for (int i = 0; i < 2; i++) {
        int r  = m0 + ar + i * 64;
        int rc = (r < cnt) ? r : (cnt - 1);   // clamp (rows >= cnt never stored)
        aptr[i] = x + (size_t)g_tok[base + rc] * DM;
    }
    // B global-load mapping: k-rows (tid>>5) + {0,8,16,24}; cols 4*(tid&31)
    const int bkr = tid >> 5;
    const int bnc = (tid & 31) * 4;
    const float* W = ew + (size_t)e * DM * DM + n0;

    float acc[4][4][4];
#pragma unroll
    for (int mi = 0; mi < 4; mi++)
#pragma unroll
        for (int ni = 0; ni < 4; ni++)
#pragma unroll
            for (int q = 0; q < 4; q++) acc[mi][ni][q] = 0.f;

    float4 av[2][2], bv[4];

    // ---- prologue: load tile 0 ----
#pragma unroll
    for (int i = 0; i < 2; i++)
#pragma unroll
        for (int j = 0; j < 2; j++)
            av[i][j] = *(const float4*)(aptr[i] + akb + j * 4);
#pragma unroll
    for (int j = 0; j < 4; j++)
        bv[j] = *(const float4*)(W + (size_t)(bkr + j * 8) * DM + bnc);

    // commit tile 0 to smem (convert to tf32)
#pragma unroll
    for (int i = 0; i < 2; i++)
#pragma unroll
        for (int j = 0; j < 2; j++) {
            unsigned* dst = &As[ar + i * 64][akb + j * 4];
            dst[0] = f2tf32(av[i][j].x); dst[1] = f2tf32(av[i][j].y);
            dst[2] = f2tf32(av[i][j].z); dst[3] = f2tf32(av[i][j].w);
        }
#pragma unroll
    for (int j = 0; j < 4; j++) {
        unsigned* dst = &Bs[bkr + j * 8][bnc];
        dst[0] = f2tf32(bv[j].x); dst[1] = f2tf32(bv[j].y);
        dst[2] = f2tf32(bv[j].z); dst[3] = f2tf32(bv[j].w);
    }
    __syncthreads();

    for (int kt = 0; kt < DM / 32; kt++) {
        const int knext = (kt + 1) * 32;
        const bool has_next = knext < DM;
        // ---- prefetch next tile into registers (overlaps with mma) ----
        if (has_next) {
#pragma unroll
            for (int i = 0; i < 2; i++)
#pragma unroll
                for (int j = 0; j < 2; j++)
                    av[i][j] = *(const float4*)(aptr[i] + knext + akb + j * 4);
#pragma unroll
            for (int j = 0; j < 4; j++)
                bv[j] = *(const float4*)(W + (size_t)(knext + bkr + j * 8) * DM + bnc);
        }

        // ---- compute current k-tile: 4 steps of k8 ----
#pragma unroll
        for (int s = 0; s < 4; s++) {
            const int kb = s * 8;
            unsigned a[4][4], b[4][2];
#pragma unroll
            for (int mi = 0; mi < 4; mi++) {
                const unsigned* r0 = As[wm + mi * 16 + gr];
                const unsigned* r1 = As[wm + mi * 16 + gr + 8];
                a[mi][0] = r0[kb + gc];
                a[mi][1] = r1[kb + gc];
                a[mi][2] = r0[kb + gc + 4];
                a[mi][3] = r1[kb + gc + 4];
            }
#pragma unroll
            for (int ni = 0; ni < 4; ni++) {
                b[ni][0] = Bs[kb + gc][wn + ni * 8 + gr];
                b[ni][1] = Bs[kb + gc + 4][wn + ni * 8 + gr];
            }
#pragma unroll
            for (int mi = 0; mi < 4; mi++)
#pragma unroll
                for (int ni = 0; ni < 4; ni++)
                    mma_tf32(acc[mi][ni], a[mi], b[ni]);
        }
        __syncthreads();

        // ---- commit prefetched tile to smem ----
        if (has_next) {
#pragma unroll
            for (int i = 0; i < 2; i++)
#pragma unroll
                for (int j = 0; j < 2; j++) {
                    unsigned* dst = &As[ar + i * 64][akb + j * 4];
                    dst[0] = f2tf32(av[i][j].x); dst[1] = f2tf32(av[i][j].y);
                    dst[2] = f2tf32(av[i][j].z); dst[3] = f2tf32(av[i][j].w);
                }
#pragma unroll
            for (int j = 0; j < 4; j++) {
                unsigned* dst = &Bs[bkr + j * 8][bnc];
                dst[0] = f2tf32(bv[j].x); dst[1] = f2tf32(bv[j].y);
                dst[2] = f2tf32(bv[j].z); dst[3] = f2tf32(bv[j].w);
            }
            __syncthreads();
        }
    }

    // ---- epilogue: d0/d1 -> (row, 2c), d2/d3 -> (row+8, 2c) ----
#pragma unroll
    for (int mi = 0; mi < 4; mi++) {
        int r0 = m0 + wm + mi * 16 + gr;
        int r1 = r0 + 8;
#pragma unroll
        for (int ni = 0; ni < 4; ni++) {
            int c = n0 + wn + ni * 8 + 2 * gc;
            if (r0 < cnt)
                *(float2*)(g_y + (size_t)(base + r0) * DM + c) =
                    make_float2(acc[mi][ni][0], acc[mi][ni][1]);
            if (r1 < cnt)
                *(float2*)(g_y + (size_t)(base + r1) * DM + c) =
                    make_float2(acc[mi][ni][2], acc[mi][ni][3]);
        }
    }
}

// ---------------- 5: log-domain combine (vectorized, fast intrinsics) ----------------
__device__ __forceinline__ float comb1(float g0, float g1, float ya, float yb) {
    float c = g0 * __expf(ya) + g1 * __expf(yb);
    if (c == 0.f) c = 2.220446049250313e-16f;
    return __logf(c);
}

__global__ void combine_kernel(float* __restrict__ out) {
    int n = blockIdx.x;
    int s0 = g_slot[n][0], s1 = g_slot[n][1];
    float g0 = g_gate[n][0], g1 = g_gate[n][1];
    const float4* y0 = (const float4*)(g_y + (size_t)s0 * DM);
    const float4* y1 = (const float4*)(g_y + (size_t)s1 * DM);
    float4* o = (float4*)(out + (size_t)n * DM);
    int f = threadIdx.x;                  // 128 threads * float4 = 512
    float4 a = y0[f], b = y1[f];
    float4 r;
    r.x = comb1(g0, g1, a.x, b.x);
    r.y = comb1(g0, g1, a.y, b.y);
    r.z = comb1(g0, g1, a.z, b.z);
    r.w = comb1(g0, g1, a.w, b.w);
    o[f] = r;
}

// ---------------- 6: balance loss (deterministic reduction) ----------------
__global__ void loss_kernel(float* __restrict__ out, int out_size) {
    __shared__ float s[NE][256];
    int tid = threadIdx.x;
    float imp[NE];
#pragma unroll
    for (int e = 0; e < NE; e++) imp[e] = 0.f;
    for (int n = tid; n < NTOK; n += 256) {
#pragma unroll
        for (int k = 0; k < TOPK; k++)
            imp[g_eidx[n][k]] += g_gate[n][k];
    }
#pragma unroll
    for (int e = 0; e < NE; e++) s[e][tid] = imp[e];
    __syncthreads();
    for (int st = 128; st > 0; st >>= 1) {
        if (tid < st) {
#pragma unroll
            for (int e = 0; e < NE; e++) s[e][tid] += s[e][tid + st];
        }
        __syncthreads();
    }
    if (tid == 0) {
        float mi = 0.f, ml = 0.f;
        float iv[NE], lv[NE];
        for (int e = 0; e < NE; e++) {
            iv[e] = s[e][0];
            lv[e] = (float)g_count[e];
            mi += iv[e]; ml += lv[e];
        }
        mi *= (1.f / NE); ml *= (1.f / NE);
        float vi = 0.f, vl = 0.f;
        for (int e = 0; e < NE; e++) {
            float di = iv[e] - mi, dl = lv[e] - ml;
            vi += di * di; vl += dl * dl;
        }
        vi *= (1.f / NE); vl *= (1.f / NE);
        float loss = vi / (mi * mi + 1e-10f) + vl / (ml * ml + 1e-10f);
        if (out_size > NTOK * DM) out[NTOK * DM] = loss;
    }
}

// ---------------- launch ----------------
extern "C" void kernel_launch(void* const* d_in, const int* in_sizes, int n_in,
                              void* d_out, int out_size) {
    const float* x  = (const float*)d_in[0];   // [8192, 512]
    const float* wg = (const float*)d_in[1];   // [512, 8]
    const float* ew = (const float*)d_in[2];   // [8, 512, 512]
    float* out = (float*)d_out;                // [8192*512] ++ [1] balance_loss

    init_kernel<<<1, 32>>>();
    gate_kernel<<<NTOK / 8, 256>>>(x, wg);
    scan_kernel<<<1, 32>>>();
    assign_kernel<<<NTOK / 256, 256>>>();
    {
        dim3 grid(DM / 128, NTOK / 128, NE);   // n-tiles, m-tiles (worst case), experts
        expert_gemm<<<grid, 256>>>(x, ew);
    }
    combine_kernel<<<NTOK, 128>>>(out);
    loss_kernel<<<1, 256>>>(out, out_size);
}